// round 2
// baseline (speedup 1.0000x reference)
#include <cuda_runtime.h>
#include <cuda_bf16.h>
#include <math.h>

// Problem constants
#define NB   4096
#define VV   16
#define CC   512
#define HH   128
#define ROWS (NB * VV)          // 65536
#define GAMMA_C 1.0f
#define ALPHA_C 1.0f
#define EPS_L1 1e-12f
#define EPS_BN 1e-5f

// ---------------- scratch (device globals; no allocation) ----------------
__device__ float g_h [ROWS * CC];          // 134 MB
__device__ float g_qk[ROWS * 2 * HH];      // 67 MB: per-n [q(16x128) | k(16x128)]
__device__ float g_hp[ROWS * CC];          // 134 MB
__device__ float g_psum  [256 * CC];
__device__ float g_psumsq[256 * CC];
__device__ float g_scale[CC];
__device__ float g_shift[CC];

// ---------------- GEMM 1: g_h = X @ W^T --------------------------------
// A: [M,K] row-major, B: [N,K] row-major (both K-contiguous, "NT" layout)
#define BM 128
#define BN 128
#define BK 16
#define TM 8
#define TN 8
#define PAD 4

__global__ __launch_bounds__(256)
void sgemm_h(const float* __restrict__ A,
             const float* __restrict__ B) {
    __shared__ float As[BK][BM + PAD];
    __shared__ float Bs[BK][BN + PAD];

    const int tid = threadIdx.x;
    const int tx  = tid & 15;
    const int ty  = tid >> 4;
    const int bm  = blockIdx.y * BM;
    const int bn  = blockIdx.x * BN;

    float acc[TM][TN];
#pragma unroll
    for (int i = 0; i < TM; ++i)
#pragma unroll
        for (int j = 0; j < TN; ++j) acc[i][j] = 0.f;

    const int lrow = tid >> 2;             // 0..63
    const int lk   = (tid & 3) * 4;        // 0,4,8,12

    for (int k0 = 0; k0 < CC; k0 += BK) {
#pragma unroll
        for (int p = 0; p < 2; ++p) {
            int row = lrow + p * 64;
            float4 va = *reinterpret_cast<const float4*>(&A[(long)(bm + row) * CC + k0 + lk]);
            As[lk + 0][row] = va.x; As[lk + 1][row] = va.y;
            As[lk + 2][row] = va.z; As[lk + 3][row] = va.w;
            float4 vb = *reinterpret_cast<const float4*>(&B[(long)(bn + row) * CC + k0 + lk]);
            Bs[lk + 0][row] = vb.x; Bs[lk + 1][row] = vb.y;
            Bs[lk + 2][row] = vb.z; Bs[lk + 3][row] = vb.w;
        }
        __syncthreads();

#pragma unroll
        for (int kk = 0; kk < BK; ++kk) {
            float a[TM], b[TN];
#pragma unroll
            for (int i = 0; i < TM; i += 4) {
                float4 v = *reinterpret_cast<const float4*>(&As[kk][ty * TM + i]);
                a[i] = v.x; a[i + 1] = v.y; a[i + 2] = v.z; a[i + 3] = v.w;
            }
#pragma unroll
            for (int j = 0; j < TN; j += 4) {
                float4 v = *reinterpret_cast<const float4*>(&Bs[kk][tx * TN + j]);
                b[j] = v.x; b[j + 1] = v.y; b[j + 2] = v.z; b[j + 3] = v.w;
            }
#pragma unroll
            for (int i = 0; i < TM; ++i)
#pragma unroll
                for (int j = 0; j < TN; ++j)
                    acc[i][j] = fmaf(a[i], b[j], acc[i][j]);
        }
        __syncthreads();
    }

#pragma unroll
    for (int i = 0; i < TM; ++i) {
        long row = bm + ty * TM + i;
#pragma unroll
        for (int j = 0; j < TN; j += 4) {
            int col = bn + tx * TN + j;
            float4 v;
            v.x = acc[i][j + 0]; v.y = acc[i][j + 1];
            v.z = acc[i][j + 2]; v.w = acc[i][j + 3];
            *reinterpret_cast<float4*>(&g_h[row * CC + col]) = v;
        }
    }
}

// ---------------- GEMM 2: fused q,k = h @ {Wq,Wk}^T + {bq,bk} ------------
// One pass over g_h computes BOTH q and k (halves h re-read traffic).
// Output layout: g_qk[n][0:VV*HH] = q rows, g_qk[n][VV*HH:2*VV*HH] = k rows.
// Logical N dim = 256: cols 0..127 -> q (B=Wq), 128..255 -> k (B=Wk).
__global__ __launch_bounds__(256)
void sgemm_qk(const float* __restrict__ Wq, const float* __restrict__ bq,
              const float* __restrict__ Wk, const float* __restrict__ bk) {
    __shared__ float As[BK][BM + PAD];
    __shared__ float Bs[BK][256 + PAD];   // 128 q cols + 128 k cols

    const int tid = threadIdx.x;
    const int tx  = tid & 31;             // 0..31 -> 256 cols / TN
    const int ty  = tid >> 5;             // 0..7  -> 128 rows / 16? -> TM=16
    const int bm  = blockIdx.x * BM;

    // 256 threads: 32x8 layout, each thread TM2=16 rows x TN2=8 cols? That's 128 regs.
    // Keep 8x8 per thread instead: use 16 tx * 16 ty won't cover 256 cols.
    // Use TMq=8 rows (ty 0..15 => need 16), redo: tx 0..31 covers cols (31*8=248.. ok 256),
    // ty 0..7 covers 8*8=64 rows -> two row-passes.
    float acc[2][TM][TN];
#pragma unroll
    for (int p = 0; p < 2; ++p)
#pragma unroll
        for (int i = 0; i < TM; ++i)
#pragma unroll
            for (int j = 0; j < TN; ++j) acc[p][i][j] = 0.f;

    const int lrow = tid >> 2;             // 0..63
    const int lk   = (tid & 3) * 4;

    for (int k0 = 0; k0 < CC; k0 += BK) {
#pragma unroll
        for (int p = 0; p < 2; ++p) {
            int row = lrow + p * 64;
            float4 va = *reinterpret_cast<const float4*>(&g_h[(long)(bm + row) * CC + k0 + lk]);
            As[lk + 0][row] = va.x; As[lk + 1][row] = va.y;
            As[lk + 2][row] = va.z; As[lk + 3][row] = va.w;
            // cols: rows 0..63 of pass p map to Wq (p=0) rows 0..127 / Wk (p=1)
            const float* Bsrc = (row < 128) ? Wq : Wk;
            int brow = row & 127;
            float4 vb = *reinterpret_cast<const float4*>(&Bsrc[(long)brow * CC + k0 + lk]);
            int c = (row < 128) ? row : (128 + brow);
            Bs[lk + 0][c] = vb.x; Bs[lk + 1][c] = vb.y;
            Bs[lk + 2][c] = vb.z; Bs[lk + 3][c] = vb.w;
        }
        __syncthreads();

#pragma unroll
        for (int kk = 0; kk < BK; ++kk) {
            float b[TN];
#pragma unroll
            for (int j = 0; j < TN; j += 4) {
                float4 v = *reinterpret_cast<const float4*>(&Bs[kk][tx * TN + j]);
                b[j] = v.x; b[j + 1] = v.y; b[j + 2] = v.z; b[j + 3] = v.w;
            }
#pragma unroll
            for (int p = 0; p < 2; ++p) {
                float a[TM];
#pragma unroll
                for (int i = 0; i < TM; i += 4) {
                    float4 v = *reinterpret_cast<const float4*>(&As[kk][p * 64 + ty * TM + i]);
                    a[i] = v.x; a[i + 1] = v.y; a[i + 2] = v.z; a[i + 3] = v.w;
                }
#pragma unroll
                for (int i = 0; i < TM; ++i)
#pragma unroll
                    for (int j = 0; j < TN; ++j)
                        acc[p][i][j] = fmaf(a[i], b[j], acc[p][i][j]);
            }
        }
        __syncthreads();
    }

    // store: col < 128 -> q, col >= 128 -> k. bias added here.
    const int colbase = tx * TN;                 // 0..248
    const bool is_k = (colbase >= 128);
    const int hcol = colbase & 127;
    float bv[TN];
#pragma unroll
    for (int j = 0; j < TN; ++j)
        bv[j] = is_k ? bk[hcol + j] : bq[hcol + j];

#pragma unroll
    for (int p = 0; p < 2; ++p) {
#pragma unroll
        for (int i = 0; i < TM; ++i) {
            long row = bm + p * 64 + ty * TM + i;       // global h-row
            long n   = row >> 4;                         // batch
            long v   = row & 15;                         // vertex
            // q block then k block inside each n
            float* dst = g_qk + n * (2 * VV * HH) + (is_k ? VV * HH : 0) + v * HH + hcol;
            float4 o;
            o.x = acc[p][i][0 + (0)] + bv[0];
            // write 8 cols as two float4
            float4 o0, o1;
            o0.x = acc[p][i][0] + bv[0]; o0.y = acc[p][i][1] + bv[1];
            o0.z = acc[p][i][2] + bv[2]; o0.w = acc[p][i][3] + bv[3];
            o1.x = acc[p][i][4] + bv[4]; o1.y = acc[p][i][5] + bv[5];
            o1.z = acc[p][i][6] + bv[6]; o1.w = acc[p][i][7] + bv[7];
            *reinterpret_cast<float4*>(dst)     = o0;
            *reinterpret_cast<float4*>(dst + 4) = o1;
            (void)o;
        }
    }
}

// ---------------- per-n attention + message passing ----------------------
__global__ __launch_bounds__(256)
void attn_kernel(const float* __restrict__ adj) {
    const int n   = blockIdx.x;
    const int tid = threadIdx.x;

    __shared__ float buf[VV * CC];       // 32KB: first q|k, then h
    __shared__ float logits[VV][VV];
    __shared__ float graph[VV][VV];

    // q|k contiguous: 4096 floats
    const float* qkg = g_qk + (long)n * 2 * VV * HH;
    for (int i = tid; i < 2 * VV * HH; i += 256) buf[i] = qkg[i];
    __syncthreads();

    {   // 256 logits, one per thread
        int v = tid >> 4, w = tid & 15;
        float s = 0.f;
        const float* qr = buf + v * HH;
        const float* kr = buf + VV * HH + w * HH;
#pragma unroll 8
        for (int c = 0; c < HH; ++c) s = fmaf(qr[c], kr[c], s);
        logits[v][w] = s;
    }
    __syncthreads();

    if (tid < VV) {
        int v = tid;
        float m = -1e30f;
#pragma unroll
        for (int w = 0; w < VV; ++w) m = fmaxf(m, logits[v][w]);
        float e[VV]; float s = 0.f;
#pragma unroll
        for (int w = 0; w < VV; ++w) { e[w] = expf(logits[v][w] - m); s += e[w]; }
        const float* arow = adj + (long)n * VV * VV + v * VV;
        float rs = 0.f;
#pragma unroll
        for (int w = 0; w < VV; ++w) rs += fabsf(arow[w]);
        rs = fmaxf(rs, EPS_L1);
        float inv_s = 1.f / s, inv_rs = 1.f / rs, inv_g = 1.f / (1.f + GAMMA_C);
#pragma unroll
        for (int w = 0; w < VV; ++w)
            graph[v][w] = (arow[w] * inv_rs + GAMMA_C * (e[w] * inv_s)) * inv_g;
    }
    __syncthreads();

    // reload buf with h_n, then hp = relu(graph @ h_n)
    const float* hg = g_h + (long)n * VV * CC;
    for (int i = tid; i < VV * CC; i += 256) buf[i] = hg[i];
    __syncthreads();

    float* outb = g_hp + (long)n * VV * CC;
    for (int cc = tid; cc < CC; cc += 256) {
        float hv[VV];
#pragma unroll
        for (int w = 0; w < VV; ++w) hv[w] = buf[w * CC + cc];
#pragma unroll
        for (int v = 0; v < VV; ++v) {
            float s = 0.f;
#pragma unroll
            for (int w = 0; w < VV; ++w) s = fmaf(graph[v][w], hv[w], s);
            outb[v * CC + cc] = fmaxf(s, 0.f);
        }
    }
}

// ---------------- BatchNorm stats: two-pass deterministic ----------------
__global__ __launch_bounds__(256)
void bn_stats1() {
    const int b   = blockIdx.x;          // 256 blocks, 256 rows each
    const int c   = threadIdx.x;         // channels c and c+256
    float s0 = 0.f, q0 = 0.f, s1 = 0.f, q1 = 0.f;
    const long r0 = (long)b * 256;
    for (int r = 0; r < 256; ++r) {
        const float* row = g_hp + (r0 + r) * CC;
        float v0 = row[c];       s0 += v0; q0 = fmaf(v0, v0, q0);
        float v1 = row[c + 256]; s1 += v1; q1 = fmaf(v1, v1, q1);
    }
    g_psum  [b * CC + c]       = s0;  g_psum  [b * CC + c + 256] = s1;
    g_psumsq[b * CC + c]       = q0;  g_psumsq[b * CC + c + 256] = q1;
}

__global__ __launch_bounds__(512)
void bn_stats2(const float* __restrict__ bn_g, const float* __restrict__ bn_b) {
    const int c = threadIdx.x;           // 512 threads, one per channel
    float s = 0.f, sq = 0.f;
    for (int i = 0; i < 256; ++i) {
        s  += g_psum  [i * CC + c];
        sq += g_psumsq[i * CC + c];
    }
    const float inv_n = 1.f / (float)ROWS;
    float mean = s * inv_n;
    float var  = sq * inv_n - mean * mean;
    float sc   = bn_g[c] * rsqrtf(var + EPS_BN);
    g_scale[c] = sc;
    g_shift[c] = bn_b[c] - mean * sc;
}

// ---------------- epilogue: out = x + alpha*(hp*scale + shift) -----------
__global__ __launch_bounds__(256)
void bn_finalize(const float* __restrict__ x, float* __restrict__ out) {
    const long i  = (long)blockIdx.x * 256 + threadIdx.x;  // float4 index
    const int  c4 = (int)(i & 127);
    float4 xv = reinterpret_cast<const float4*>(x)[i];
    float4 hv = reinterpret_cast<const float4*>(g_hp)[i];
    float4 sc = reinterpret_cast<const float4*>(g_scale)[c4];
    float4 sh = reinterpret_cast<const float4*>(g_shift)[c4];
    float4 o;
    o.x = xv.x + ALPHA_C * fmaf(hv.x, sc.x, sh.x);
    o.y = xv.y + ALPHA_C * fmaf(hv.y, sc.y, sh.y);
    o.z = xv.z + ALPHA_C * fmaf(hv.z, sc.z, sh.z);
    o.w = xv.w + ALPHA_C * fmaf(hv.w, sc.w, sh.w);
    reinterpret_cast<float4*>(out)[i] = o;
}

// ---------------- launch ----------------
extern "C" void kernel_launch(void* const* d_in, const int* in_sizes, int n_in,
                              void* d_out, int out_size) {
    const float* x    = (const float*)d_in[0];
    const float* adj  = (const float*)d_in[1];
    const float* W    = (const float*)d_in[2];
    const float* Wq   = (const float*)d_in[3];
    const float* bq   = (const float*)d_in[4];
    const float* Wk   = (const float*)d_in[5];
    const float* bk   = (const float*)d_in[6];
    const float* bn_g = (const float*)d_in[7];
    const float* bn_b = (const float*)d_in[8];
    float* out = (float*)d_out;

    // h = X @ W^T                      [65536,512]
    sgemm_h<<<dim3(CC / BN, ROWS / BM), 256>>>(x, W);
    // q,k = h @ {Wq,Wk}^T + bias (fused; one read of h)
    sgemm_qk<<<ROWS / BM, 256>>>(Wq, bq, Wk, bk);
    // attention + message passing -> hp
    attn_kernel<<<NB, 256>>>(adj);
    // BN stats (deterministic tree)
    bn_stats1<<<256, 256>>>();
    bn_stats2<<<1, 512>>>(bn_g, bn_b);
    // residual + affine
    bn_finalize<<<(ROWS * CC / 4) / 256, 256>>>(x, out);
}

// round 7
// speedup vs baseline: 1.5323x; 1.5323x over previous
#include <cuda_runtime.h>
#include <cuda_bf16.h>
#include <cstdint>
#include <math.h>

// Problem constants
#define NB   4096
#define VV   16
#define CC   512
#define HH   128
#define ROWS (NB * VV)          // 65536
#define NOUT 768                // h(512) | q(128) | k(128)
#define GAMMA_C 1.0f
#define ALPHA_C 1.0f
#define EPS_L1 1e-12f
#define EPS_BN 1e-5f

// ---------------- scratch (device globals; no allocation) ----------------
__device__ float g_h [ROWS * CC];                       // 134 MB
__device__ float g_qk[ROWS * 2 * HH];                   // 67 MB per-n [q|k]
__device__ float g_hp[ROWS * CC];                       // 134 MB
__device__ __align__(16) __nv_bfloat16 g_xhi[ROWS * CC];   // 67 MB
__device__ __align__(16) __nv_bfloat16 g_xlo[ROWS * CC];   // 67 MB
__device__ float g_cw[256 * CC];                        // WqW | WkW (fp32)
__device__ __align__(16) __nv_bfloat16 g_cwhi[NOUT * CC];
__device__ __align__(16) __nv_bfloat16 g_cwlo[NOUT * CC];
__device__ float g_psum  [256 * CC];
__device__ float g_psumsq[256 * CC];
__device__ float g_scale[CC];
__device__ float g_shift[CC];

// ---------------- prep: split x into bf16 hi/lo --------------------------
__global__ __launch_bounds__(256)
void xsplit(const float* __restrict__ x) {
    const long i = (long)blockIdx.x * 256 + threadIdx.x;      // float4 idx
    float4 v = reinterpret_cast<const float4*>(x)[i];
    __nv_bfloat16 hx = __float2bfloat16(v.x), hy = __float2bfloat16(v.y);
    __nv_bfloat16 hz = __float2bfloat16(v.z), hw = __float2bfloat16(v.w);
    __nv_bfloat162 h01; h01.x = hx; h01.y = hy;
    __nv_bfloat162 h23; h23.x = hz; h23.y = hw;
    __nv_bfloat162 l01, l23;
    l01.x = __float2bfloat16(v.x - __bfloat162float(hx));
    l01.y = __float2bfloat16(v.y - __bfloat162float(hy));
    l23.x = __float2bfloat16(v.z - __bfloat162float(hz));
    l23.y = __float2bfloat16(v.w - __bfloat162float(hw));
    reinterpret_cast<__nv_bfloat162*>(g_xhi)[2 * i]     = h01;
    reinterpret_cast<__nv_bfloat162*>(g_xhi)[2 * i + 1] = h23;
    reinterpret_cast<__nv_bfloat162*>(g_xlo)[2 * i]     = l01;
    reinterpret_cast<__nv_bfloat162*>(g_xlo)[2 * i + 1] = l23;
}

// ---------------- prep: CW rows for q,k = {Wq,Wk} @ W (fp32) -------------
__global__ __launch_bounds__(512)
void wprep(const float* __restrict__ W, const float* __restrict__ Wq,
           const float* __restrict__ Wk) {
    const int o = blockIdx.x;            // 0..255
    const int c = threadIdx.x;           // 0..511
    const float* Ws = (o < 128) ? Wq : Wk;
    const int oo = o & 127;
    float acc = 0.f;
    for (int j = 0; j < CC; ++j)
        acc = fmaf(Ws[oo * CC + j], W[j * CC + c], acc);
    g_cw[o * CC + c] = acc;
}

// ---------------- prep: split combined weight [W; WqW; WkW] to bf16 ------
__global__ __launch_bounds__(256)
void wsplit(const float* __restrict__ W) {
    const int i = blockIdx.x * 256 + threadIdx.x;   // 0 .. 768*512-1
    const int row = i >> 9;
    const int col = i & 511;
    float v = (row < CC) ? W[i] : g_cw[(row - CC) * CC + col];
    __nv_bfloat16 hi = __float2bfloat16(v);
    g_cwhi[i] = hi;
    g_cwlo[i] = __float2bfloat16(v - __bfloat162float(hi));
}

// ================= main GEMM: [h|q|k] = x @ CW^T ==========================
// mma.sync bf16x3 (generic PTX; tcgen05 unavailable under compute_103 target)
// Block tile M=128 N=128 K=32, 8 warps (2x4), warp tile 64x32.
// smem rows padded to 80B: conflict-free fragment LDS, 16B-aligned cp.async.

#define ROW_B 80                         // bytes per 32-bf16 row (64B data + 16B pad)
#define TILE_B (128 * ROW_B)             // 10240 per operand tile
#define STAGE_B (4 * TILE_B)             // Ahi|Alo|Bhi|Blo = 40960
#define SMEM_GEMM (2 * STAGE_B)          // 81920 double-buffered

__device__ __forceinline__ uint32_t smem_u32(const void* p) {
    uint32_t a;
    asm("{ .reg .u64 t; cvta.to.shared.u64 t, %1; cvt.u32.u64 %0, t; }" : "=r"(a) : "l"(p));
    return a;
}

#define CP16(dst, src) \
    asm volatile("cp.async.cg.shared.global [%0], [%1], 16;" :: "r"(dst), "l"(src))

#define MMA_BF16(d, a, b) \
    asm volatile("mma.sync.aligned.m16n8k16.row.col.f32.bf16.bf16.f32 " \
        "{%0,%1,%2,%3}, {%4,%5,%6,%7}, {%8,%9}, {%0,%1,%2,%3};" \
        : "+f"((d)[0]), "+f"((d)[1]), "+f"((d)[2]), "+f"((d)[3]) \
        : "r"((a)[0]), "r"((a)[1]), "r"((a)[2]), "r"((a)[3]), \
          "r"((b)[0]), "r"((b)[1]))

__global__ __launch_bounds__(256)
void gemm_mma(const float* __restrict__ bq, const float* __restrict__ bk) {
    extern __shared__ char smem[];
    const int tid = threadIdx.x;
    const int wid = tid >> 5, lid = tid & 31;
    const int wm  = wid >> 2, wn = wid & 3;       // warp grid 2x4
    const int g   = lid >> 2, t  = lid & 3;
    const int tn  = blockIdx.x;                   // 0..5 (N tile of 128)
    const long bm = (long)blockIdx.y * 128;
    const long bn = (long)tn * 128;

    float acc[4][4][4];
#pragma unroll
    for (int i = 0; i < 4; ++i)
#pragma unroll
        for (int j = 0; j < 4; ++j)
#pragma unroll
            for (int r = 0; r < 4; ++r) acc[i][j][r] = 0.f;

    // --- stage loader: 2048 16B chunks, 8 per thread; tile = u>>1 (static)
    const int lrow = tid >> 2;        // 0..63
    const int lcc  = tid & 3;         // 16B chunk in row
#define LOAD_STAGE(sbuf, k0)                                                     \
    do {                                                                         \
        char* base_ = smem + (sbuf) * STAGE_B;                                   \
        _Pragma("unroll")                                                        \
        for (int u = 0; u < 8; ++u) {                                            \
            const int tile_ = u >> 1;                                            \
            const int row_  = lrow + (u & 1) * 64;                               \
            const __nv_bfloat16* gs_;                                            \
            if      (tile_ == 0) gs_ = g_xhi  + (bm + row_) * CC + (k0) + lcc * 8; \
            else if (tile_ == 1) gs_ = g_xlo  + (bm + row_) * CC + (k0) + lcc * 8; \
            else if (tile_ == 2) gs_ = g_cwhi + (bn + row_) * CC + (k0) + lcc * 8; \
            else                 gs_ = g_cwlo + (bn + row_) * CC + (k0) + lcc * 8; \
            uint32_t d_ = smem_u32(base_ + tile_ * TILE_B + row_ * ROW_B + lcc * 16); \
            CP16(d_, gs_);                                                       \
        }                                                                        \
        asm volatile("cp.async.commit_group;");                                  \
    } while (0)

    LOAD_STAGE(0, 0);

    for (int s = 0; s < 16; ++s) {
        if (s + 1 < 16) {
            LOAD_STAGE((s + 1) & 1, (s + 1) * 32);
            asm volatile("cp.async.wait_group 1;");
        } else {
            asm volatile("cp.async.wait_group 0;");
        }
        __syncthreads();

        const char* base = smem + (s & 1) * STAGE_B;
        const char* Ahi = base;
        const char* Alo = base + TILE_B;
        const char* Bhi = base + 2 * TILE_B;
        const char* Blo = base + 3 * TILE_B;

#pragma unroll
        for (int kk = 0; kk < 2; ++kk) {
            const int cby = kk * 32 + t * 4;      // byte offset of col pair
            uint32_t ah[4][4], al[4][4], bh[4][2], bl[4][2];
#pragma unroll
            for (int i = 0; i < 4; ++i) {
                const int r0 = wm * 64 + i * 16 + g;
                ah[i][0] = *(const uint32_t*)(Ahi + r0 * ROW_B + cby);
                ah[i][1] = *(const uint32_t*)(Ahi + (r0 + 8) * ROW_B + cby);
                ah[i][2] = *(const uint32_t*)(Ahi + r0 * ROW_B + cby + 16);
                ah[i][3] = *(const uint32_t*)(Ahi + (r0 + 8) * ROW_B + cby + 16);
                al[i][0] = *(const uint32_t*)(Alo + r0 * ROW_B + cby);
                al[i][1] = *(const uint32_t*)(Alo + (r0 + 8) * ROW_B + cby);
                al[i][2] = *(const uint32_t*)(Alo + r0 * ROW_B + cby + 16);
                al[i][3] = *(const uint32_t*)(Alo + (r0 + 8) * ROW_B + cby + 16);
            }
#pragma unroll
            for (int j = 0; j < 4; ++j) {
                const int n = wn * 32 + j * 8 + g;
                bh[j][0] = *(const uint32_t*)(Bhi + n * ROW_B + cby);
                bh[j][1] = *(const uint32_t*)(Bhi + n * ROW_B + cby + 16);
                bl[j][0] = *(const uint32_t*)(Blo + n * ROW_B + cby);
                bl[j][1] = *(const uint32_t*)(Blo + n * ROW_B + cby + 16);
            }
#pragma unroll
            for (int i = 0; i < 4; ++i)
#pragma unroll
                for (int j = 0; j < 4; ++j) {
                    MMA_BF16(acc[i][j], ah[i], bh[j]);
                    MMA_BF16(acc[i][j], ah[i], bl[j]);
                    MMA_BF16(acc[i][j], al[i], bh[j]);
                }
        }
        __syncthreads();   // compute done before next stage overwrites buffer
    }

    // --- epilogue: D rows g/g+8, cols t*2,t*2+1 per (i,j)
#pragma unroll
    for (int i = 0; i < 4; ++i) {
#pragma unroll
        for (int j = 0; j < 4; ++j) {
            const int coll = wn * 32 + j * 8 + t * 2;     // 0..127 within block
#pragma unroll
            for (int half = 0; half < 2; ++half) {
                const long grow = bm + wm * 64 + i * 16 + g + half * 8;
                float v0 = acc[i][j][half * 2 + 0];
                float v1 = acc[i][j][half * 2 + 1];
                if (tn < 4) {
                    float2 o; o.x = v0; o.y = v1;
                    *reinterpret_cast<float2*>(&g_h[grow * CC + tn * 128 + coll]) = o;
                } else {
                    const float* bias = (tn == 4) ? bq : bk;
                    float2 o; o.x = v0 + bias[coll]; o.y = v1 + bias[coll + 1];
                    float* dst = g_qk + (grow >> 4) * (2 * VV * HH)
                               + ((tn == 5) ? VV * HH : 0) + (grow & 15) * HH + coll;
                    *reinterpret_cast<float2*>(dst) = o;
                }
            }
        }
    }
}

// ---------------- per-n attention + message passing ----------------------
__global__ __launch_bounds__(256)
void attn_kernel(const float* __restrict__ adj) {
    const int n   = blockIdx.x;
    const int tid = threadIdx.x;

    __shared__ float buf[VV * CC];       // 32KB: first q|k, then h
    __shared__ float logits[VV][VV];
    __shared__ float graph[VV][VV];

    const float* qkg = g_qk + (long)n * 2 * VV * HH;
    for (int i = tid; i < 2 * VV * HH; i += 256) buf[i] = qkg[i];
    __syncthreads();

    {
        int v = tid >> 4, w = tid & 15;
        float s = 0.f;
        const float* qr = buf + v * HH;
        const float* kr = buf + VV * HH + w * HH;
#pragma unroll 8
        for (int c = 0; c < HH; ++c) s = fmaf(qr[c], kr[c], s);
        logits[v][w] = s;
    }
    __syncthreads();

    if (tid < VV) {
        int v = tid;
        float m = -1e30f;
#pragma unroll
        for (int w = 0; w < VV; ++w) m = fmaxf(m, logits[v][w]);
        float e[VV]; float s = 0.f;
#pragma unroll
        for (int w = 0; w < VV; ++w) { e[w] = expf(logits[v][w] - m); s += e[w]; }
        const float* arow = adj + (long)n * VV * VV + v * VV;
        float rs = 0.f;
#pragma unroll
        for (int w = 0; w < VV; ++w) rs += fabsf(arow[w]);
        rs = fmaxf(rs, EPS_L1);
        float inv_s = 1.f / s, inv_rs = 1.f / rs, inv_g = 1.f / (1.f + GAMMA_C);
#pragma unroll
        for (int w = 0; w < VV; ++w)
            graph[v][w] = (arow[w] * inv_rs + GAMMA_C * (e[w] * inv_s)) * inv_g;
    }
    __syncthreads();

    const float* hg = g_h + (long)n * VV * CC;
    for (int i = tid; i < VV * CC; i += 256) buf[i] = hg[i];
    __syncthreads();

    float* outb = g_hp + (long)n * VV * CC;
    for (int cc = tid; cc < CC; cc += 256) {
        float hv[VV];
#pragma unroll
        for (int w = 0; w < VV; ++w) hv[w] = buf[w * CC + cc];
#pragma unroll
        for (int v = 0; v < VV; ++v) {
            float s = 0.f;
#pragma unroll
            for (int w = 0; w < VV; ++w) s = fmaf(graph[v][w], hv[w], s);
            outb[v * CC + cc] = fmaxf(s, 0.f);
        }
    }
}

// ---------------- BatchNorm stats: two-pass deterministic ----------------
__global__ __launch_bounds__(256)
void bn_stats1() {
    const int b = blockIdx.x;
    const int c = threadIdx.x;
    float s0 = 0.f, q0 = 0.f, s1 = 0.f, q1 = 0.f;
    const long r0 = (long)b * 256;
    for (int r = 0; r < 256; ++r) {
        const float* row = g_hp + (r0 + r) * CC;
        float v0 = row[c];       s0 += v0; q0 = fmaf(v0, v0, q0);
        float v1 = row[c + 256]; s1 += v1; q1 = fmaf(v1, v1, q1);
    }
    g_psum  [b * CC + c]       = s0;  g_psum  [b * CC + c + 256] = s1;
    g_psumsq[b * CC + c]       = q0;  g_psumsq[b * CC + c + 256] = q1;
}

__global__ __launch_bounds__(512)
void bn_stats2(const float* __restrict__ bn_g, const float* __restrict__ bn_b) {
    const int c = threadIdx.x;
    float s = 0.f, sq = 0.f;
    for (int i = 0; i < 256; ++i) {
        s  += g_psum  [i * CC + c];
        sq += g_psumsq[i * CC + c];
    }
    const float inv_n = 1.f / (float)ROWS;
    float mean = s * inv_n;
    float var  = sq * inv_n - mean * mean;
    float sc   = bn_g[c] * rsqrtf(var + EPS_BN);
    g_scale[c] = sc;
    g_shift[c] = bn_b[c] - mean * sc;
}

// ---------------- epilogue: out = x + alpha*(hp*scale + shift) -----------
__global__ __launch_bounds__(256)
void bn_finalize(const float* __restrict__ x, float* __restrict__ out) {
    const long i  = (long)blockIdx.x * 256 + threadIdx.x;
    const int  c4 = (int)(i & 127);
    float4 xv = reinterpret_cast<const float4*>(x)[i];
    float4 hv = reinterpret_cast<const float4*>(g_hp)[i];
    float4 sc = reinterpret_cast<const float4*>(g_scale)[c4];
    float4 sh = reinterpret_cast<const float4*>(g_shift)[c4];
    float4 o;
    o.x = xv.x + ALPHA_C * fmaf(hv.x, sc.x, sh.x);
    o.y = xv.y + ALPHA_C * fmaf(hv.y, sc.y, sh.y);
    o.z = xv.z + ALPHA_C * fmaf(hv.z, sc.z, sh.z);
    o.w = xv.w + ALPHA_C * fmaf(hv.w, sc.w, sh.w);
    reinterpret_cast<float4*>(out)[i] = o;
}

// ---------------- launch ----------------
extern "C" void kernel_launch(void* const* d_in, const int* in_sizes, int n_in,
                              void* d_out, int out_size) {
    const float* x    = (const float*)d_in[0];
    const float* adj  = (const float*)d_in[1];
    const float* W    = (const float*)d_in[2];
    const float* Wq   = (const float*)d_in[3];
    const float* bq   = (const float*)d_in[4];
    const float* Wk   = (const float*)d_in[5];
    const float* bk   = (const float*)d_in[6];
    const float* bn_g = (const float*)d_in[7];
    const float* bn_b = (const float*)d_in[8];
    float* out = (float*)d_out;

    cudaFuncSetAttribute(gemm_mma, cudaFuncAttributeMaxDynamicSharedMemorySize, SMEM_GEMM);

    // prep: split x; build combined weight [W; WqW; WkW] and split
    xsplit<<<(ROWS * CC / 4) / 256, 256>>>(x);
    wprep<<<256, 512>>>(W, Wq, Wk);
    wsplit<<<(NOUT * CC) / 256, 256>>>(W);
    // [h | q | k] = x @ CW^T   (mma.sync bf16x3)
    gemm_mma<<<dim3(6, 512), 256, SMEM_GEMM>>>(bq, bk);
    // attention + message passing -> hp
    attn_kernel<<<NB, 256>>>(adj);
    // BN stats + epilogue
    bn_stats1<<<256, 256>>>();
    bn_stats2<<<1, 512>>>(bn_g, bn_b);
    bn_finalize<<<(ROWS * CC / 4) / 256, 256>>>(x, out);
}

// round 11
// speedup vs baseline: 1.5527x; 1.0133x over previous
#include <cuda_runtime.h>
#include <cuda_bf16.h>
#include <cstdint>
#include <math.h>

// Problem constants
#define NB   4096
#define VV   16
#define CC   512
#define HH   128
#define ROWS (NB * VV)          // 65536
#define NOUT 768                // h(512) | q(128) | k(128)
#define GAMMA_C 1.0f
#define ALPHA_C 1.0f
#define EPS_L1 1e-12f
#define EPS_BN 1e-5f

// ---------------- scratch (device globals; no allocation) ----------------
__device__ float g_h [ROWS * CC];                       // 134 MB
__device__ float g_qk[ROWS * 2 * HH];                   // 67 MB per-n [q|k]
__device__ float g_hp[ROWS * CC];                       // 134 MB
__device__ __align__(16) __nv_bfloat16 g_xhi[ROWS * CC];   // 67 MB
__device__ __align__(16) __nv_bfloat16 g_xlo[ROWS * CC];   // 67 MB
__device__ float g_cw[256 * CC];                        // WqW | WkW (fp32)
__device__ __align__(16) __nv_bfloat16 g_cwhi[NOUT * CC];
__device__ __align__(16) __nv_bfloat16 g_cwlo[NOUT * CC];
__device__ float g_bsum  [NB * CC];                     // per-batch partial sums
__device__ float g_bsumsq[NB * CC];
__device__ float g_psum  [256 * CC];
__device__ float g_psumsq[256 * CC];
__device__ float g_scale[CC];
__device__ float g_shift[CC];

// ---------------- prep: split x into bf16 hi/lo --------------------------
__global__ __launch_bounds__(256)
void xsplit(const float* __restrict__ x) {
    const long i = (long)blockIdx.x * 256 + threadIdx.x;      // float4 idx
    float4 v = reinterpret_cast<const float4*>(x)[i];
    __nv_bfloat16 hx = __float2bfloat16(v.x), hy = __float2bfloat16(v.y);
    __nv_bfloat16 hz = __float2bfloat16(v.z), hw = __float2bfloat16(v.w);
    __nv_bfloat162 h01; h01.x = hx; h01.y = hy;
    __nv_bfloat162 h23; h23.x = hz; h23.y = hw;
    __nv_bfloat162 l01, l23;
    l01.x = __float2bfloat16(v.x - __bfloat162float(hx));
    l01.y = __float2bfloat16(v.y - __bfloat162float(hy));
    l23.x = __float2bfloat16(v.z - __bfloat162float(hz));
    l23.y = __float2bfloat16(v.w - __bfloat162float(hw));
    reinterpret_cast<__nv_bfloat162*>(g_xhi)[2 * i]     = h01;
    reinterpret_cast<__nv_bfloat162*>(g_xhi)[2 * i + 1] = h23;
    reinterpret_cast<__nv_bfloat162*>(g_xlo)[2 * i]     = l01;
    reinterpret_cast<__nv_bfloat162*>(g_xlo)[2 * i + 1] = l23;
}

// ---------------- prep: CW rows for q,k = {Wq,Wk} @ W (fp32) -------------
__global__ __launch_bounds__(512)
void wprep(const float* __restrict__ W, const float* __restrict__ Wq,
           const float* __restrict__ Wk) {
    const int o = blockIdx.x;            // 0..255
    const int c = threadIdx.x;           // 0..511
    const float* Ws = (o < 128) ? Wq : Wk;
    const int oo = o & 127;
    float acc = 0.f;
    for (int j = 0; j < CC; ++j)
        acc = fmaf(Ws[oo * CC + j], W[j * CC + c], acc);
    g_cw[o * CC + c] = acc;
}

// ---------------- prep: split combined weight [W; WqW; WkW] to bf16 ------
__global__ __launch_bounds__(256)
void wsplit(const float* __restrict__ W) {
    const int i = blockIdx.x * 256 + threadIdx.x;   // 0 .. 768*512-1
    const int row = i >> 9;
    const int col = i & 511;
    float v = (row < CC) ? W[i] : g_cw[(row - CC) * CC + col];
    __nv_bfloat16 hi = __float2bfloat16(v);
    g_cwhi[i] = hi;
    g_cwlo[i] = __float2bfloat16(v - __bfloat162float(hi));
}

// ================= main GEMM: [h|q|k] = x @ CW^T ==========================
// mma.sync bf16x3 + ldmatrix fragments; cp.async double-buffered K=32 stages.
// Block tile M=128 N=128, 8 warps (2x4), warp tile 64x32.
// smem rows padded to 80B: ldmatrix phases hit all 32 banks exactly once.

#define ROW_B 80                         // bytes per 32-bf16 row (64B data + 16B pad)
#define TILE_B (128 * ROW_B)             // 10240 per operand tile
#define STAGE_B (4 * TILE_B)             // Ahi|Alo|Bhi|Blo = 40960
#define SMEM_GEMM (2 * STAGE_B)          // 81920 double-buffered

__device__ __forceinline__ uint32_t smem_u32(const void* p) {
    uint32_t a;
    asm("{ .reg .u64 t; cvta.to.shared.u64 t, %1; cvt.u32.u64 %0, t; }" : "=r"(a) : "l"(p));
    return a;
}

#define CP16(dst, src) \
    asm volatile("cp.async.cg.shared.global [%0], [%1], 16;" :: "r"(dst), "l"(src))

#define MMA_BF16(d, a, b) \
    asm volatile("mma.sync.aligned.m16n8k16.row.col.f32.bf16.bf16.f32 " \
        "{%0,%1,%2,%3}, {%4,%5,%6,%7}, {%8,%9}, {%0,%1,%2,%3};" \
        : "+f"((d)[0]), "+f"((d)[1]), "+f"((d)[2]), "+f"((d)[3]) \
        : "r"((a)[0]), "r"((a)[1]), "r"((a)[2]), "r"((a)[3]), \
          "r"((b)[0]), "r"((b)[1]))

#define LDSM4(r0, r1, r2, r3, addr) \
    asm volatile("ldmatrix.sync.aligned.m8n8.x4.shared.b16 {%0,%1,%2,%3}, [%4];" \
        : "=r"(r0), "=r"(r1), "=r"(r2), "=r"(r3) : "r"(addr))

__global__ __launch_bounds__(256, 2)
void gemm_mma(const float* __restrict__ bq, const float* __restrict__ bk) {
    extern __shared__ char smem[];
    const int tid = threadIdx.x;
    const int wid = tid >> 5, lid = tid & 31;
    const int wm  = wid >> 2, wn = wid & 3;       // warp grid 2x4
    const int g   = lid >> 2, t  = lid & 3;
    const int tn  = blockIdx.x;                   // 0..5 (N tile of 128)
    const long bm = (long)blockIdx.y * 128;
    const long bn = (long)tn * 128;

    float acc[4][4][4];
#pragma unroll
    for (int i = 0; i < 4; ++i)
#pragma unroll
        for (int j = 0; j < 4; ++j)
#pragma unroll
            for (int r = 0; r < 4; ++r) acc[i][j][r] = 0.f;

    // ldmatrix per-lane sub-addresses
    const int rin    = lid & 7;
    const int arow_l = ((lid >> 3) & 1) * 8 + rin;   // row within 16-row A frag
    const int acolt  = (lid >> 4) * 16;              // 0 or 16 bytes (k half)
    const int brow_l = (lid >> 4) * 8 + rin;         // row within 16-row B pair
    const int bcolt  = ((lid >> 3) & 1) * 16;        // 0 or 16 bytes (k half)

    const uint32_t smem0 = smem_u32(smem);

    // --- stage loader: 2048 16B chunks, 8 per thread
    const int lrow = tid >> 2;        // 0..63
    const int lcc  = tid & 3;         // 16B chunk in row
#define LOAD_STAGE(sbuf, k0)                                                     \
    do {                                                                         \
        char* base_ = smem + (sbuf) * STAGE_B;                                   \
        _Pragma("unroll")                                                        \
        for (int u = 0; u < 8; ++u) {                                            \
            const int tile_ = u >> 1;                                            \
            const int row_  = lrow + (u & 1) * 64;                               \
            const __nv_bfloat16* gs_;                                            \
            if      (tile_ == 0) gs_ = g_xhi  + (bm + row_) * CC + (k0) + lcc * 8; \
            else if (tile_ == 1) gs_ = g_xlo  + (bm + row_) * CC + (k0) + lcc * 8; \
            else if (tile_ == 2) gs_ = g_cwhi + (bn + row_) * CC + (k0) + lcc * 8; \
            else                 gs_ = g_cwlo + (bn + row_) * CC + (k0) + lcc * 8; \
            uint32_t d_ = smem_u32(base_ + tile_ * TILE_B + row_ * ROW_B + lcc * 16); \
            CP16(d_, gs_);                                                       \
        }                                                                        \
        asm volatile("cp.async.commit_group;");                                  \
    } while (0)

    LOAD_STAGE(0, 0);

    for (int s = 0; s < 16; ++s) {
        if (s + 1 < 16) {
            LOAD_STAGE((s + 1) & 1, (s + 1) * 32);
            asm volatile("cp.async.wait_group 1;");
        } else {
            asm volatile("cp.async.wait_group 0;");
        }
        __syncthreads();

        const uint32_t base = smem0 + (s & 1) * STAGE_B;
        const uint32_t Ahi = base;
        const uint32_t Alo = base + TILE_B;
        const uint32_t Bhi = base + 2 * TILE_B;
        const uint32_t Blo = base + 3 * TILE_B;

#pragma unroll
        for (int kk = 0; kk < 2; ++kk) {
            const int acol = kk * 32 + acolt;
            const int bcol = kk * 32 + bcolt;
            uint32_t ah[4][4], al[4][4], bh[4][2], bl[4][2];
#pragma unroll
            for (int i = 0; i < 4; ++i) {
                const uint32_t aoff = (uint32_t)((wm * 64 + i * 16 + arow_l) * ROW_B + acol);
                LDSM4(ah[i][0], ah[i][1], ah[i][2], ah[i][3], Ahi + aoff);
                LDSM4(al[i][0], al[i][1], al[i][2], al[i][3], Alo + aoff);
            }
#pragma unroll
            for (int p = 0; p < 2; ++p) {
                const uint32_t boff = (uint32_t)((wn * 32 + p * 16 + brow_l) * ROW_B + bcol);
                LDSM4(bh[2*p][0], bh[2*p][1], bh[2*p+1][0], bh[2*p+1][1], Bhi + boff);
                LDSM4(bl[2*p][0], bl[2*p][1], bl[2*p+1][0], bl[2*p+1][1], Blo + boff);
            }
#pragma unroll
            for (int i = 0; i < 4; ++i)
#pragma unroll
                for (int j = 0; j < 4; ++j) {
                    MMA_BF16(acc[i][j], ah[i], bh[j]);
                    MMA_BF16(acc[i][j], ah[i], bl[j]);
                    MMA_BF16(acc[i][j], al[i], bh[j]);
                }
        }
        __syncthreads();   // compute done before next stage overwrites buffer
    }

    // --- epilogue: D rows g/g+8, cols t*2,t*2+1 per (i,j)
#pragma unroll
    for (int i = 0; i < 4; ++i) {
#pragma unroll
        for (int j = 0; j < 4; ++j) {
            const int coll = wn * 32 + j * 8 + t * 2;     // 0..127 within block
#pragma unroll
            for (int half = 0; half < 2; ++half) {
                const long grow = bm + wm * 64 + i * 16 + g + half * 8;
                float v0 = acc[i][j][half * 2 + 0];
                float v1 = acc[i][j][half * 2 + 1];
                if (tn < 4) {
                    float2 o; o.x = v0; o.y = v1;
                    *reinterpret_cast<float2*>(&g_h[grow * CC + tn * 128 + coll]) = o;
                } else {
                    const float* bias = (tn == 4) ? bq : bk;
                    float2 o; o.x = v0 + bias[coll]; o.y = v1 + bias[coll + 1];
                    float* dst = g_qk + (grow >> 4) * (2 * VV * HH)
                               + ((tn == 5) ? VV * HH : 0) + (grow & 15) * HH + coll;
                    *reinterpret_cast<float2*>(dst) = o;
                }
            }
        }
    }
}

// ---------------- per-n attention + message passing + BN partials --------
__global__ __launch_bounds__(256)
void attn_kernel(const float* __restrict__ adj) {
    const int n   = blockIdx.x;
    const int tid = threadIdx.x;

    __shared__ float buf[VV * CC];       // 32KB: first q|k, then h
    __shared__ float logits[VV][VV];
    __shared__ float graph[VV][VV];

    const float* qkg = g_qk + (long)n * 2 * VV * HH;
    for (int i = tid; i < 2 * VV * HH; i += 256) buf[i] = qkg[i];
    __syncthreads();

    {
        int v = tid >> 4, w = tid & 15;
        float s = 0.f;
        const float* qr = buf + v * HH;
        const float* kr = buf + VV * HH + w * HH;
#pragma unroll 8
        for (int c = 0; c < HH; ++c) s = fmaf(qr[c], kr[c], s);
        logits[v][w] = s;
    }
    __syncthreads();

    if (tid < VV) {
        int v = tid;
        float m = -1e30f;
#pragma unroll
        for (int w = 0; w < VV; ++w) m = fmaxf(m, logits[v][w]);
        float e[VV]; float s = 0.f;
#pragma unroll
        for (int w = 0; w < VV; ++w) { e[w] = expf(logits[v][w] - m); s += e[w]; }
        const float* arow = adj + (long)n * VV * VV + v * VV;
        float rs = 0.f;
#pragma unroll
        for (int w = 0; w < VV; ++w) rs += fabsf(arow[w]);
        rs = fmaxf(rs, EPS_L1);
        float inv_s = 1.f / s, inv_rs = 1.f / rs, inv_g = 1.f / (1.f + GAMMA_C);
#pragma unroll
        for (int w = 0; w < VV; ++w)
            graph[v][w] = (arow[w] * inv_rs + GAMMA_C * (e[w] * inv_s)) * inv_g;
    }
    __syncthreads();

    const float* hg = g_h + (long)n * VV * CC;
    for (int i = tid; i < VV * CC; i += 256) buf[i] = hg[i];
    __syncthreads();

    float* outb = g_hp + (long)n * VV * CC;
    for (int cc = tid; cc < CC; cc += 256) {
        float hv[VV];
#pragma unroll
        for (int w = 0; w < VV; ++w) hv[w] = buf[w * CC + cc];
        float ps = 0.f, pq = 0.f;
#pragma unroll
        for (int v = 0; v < VV; ++v) {
            float s = 0.f;
#pragma unroll
            for (int w = 0; w < VV; ++w) s = fmaf(graph[v][w], hv[w], s);
            s = fmaxf(s, 0.f);
            outb[v * CC + cc] = s;
            ps += s;
            pq = fmaf(s, s, pq);
        }
        g_bsum  [(long)n * CC + cc] = ps;     // fused BN pass-1 partials
        g_bsumsq[(long)n * CC + cc] = pq;
    }
}

// ---------------- BN reductions (deterministic tree) ---------------------
__global__ __launch_bounds__(512)
void bn_red1() {
    const int b = blockIdx.x;            // 256 blocks, 16 batches each
    const int c = threadIdx.x;           // channel
    float s = 0.f, q = 0.f;
#pragma unroll
    for (int i = 0; i < 16; ++i) {
        const long n = (long)b * 16 + i;
        s += g_bsum  [n * CC + c];
        q += g_bsumsq[n * CC + c];
    }
    g_psum  [b * CC + c] = s;
    g_psumsq[b * CC + c] = q;
}

__global__ __launch_bounds__(512)
void bn_stats2(const float* __restrict__ bn_g, const float* __restrict__ bn_b) {
    const int c = threadIdx.x;
    float s = 0.f, sq = 0.f;
    for (int i = 0; i < 256; ++i) {
        s  += g_psum  [i * CC + c];
        sq += g_psumsq[i * CC + c];
    }
    const float inv_n = 1.f / (float)ROWS;
    float mean = s * inv_n;
    float var  = sq * inv_n - mean * mean;
    float sc   = bn_g[c] * rsqrtf(var + EPS_BN);
    g_scale[c] = sc;
    g_shift[c] = bn_b[c] - mean * sc;
}

// ---------------- epilogue: out = x + alpha*(hp*scale + shift) -----------
__global__ __launch_bounds__(256)
void bn_finalize(const float* __restrict__ x, float* __restrict__ out) {
    const long i  = (long)blockIdx.x * 256 + threadIdx.x;
    const int  c4 = (int)(i & 127);
    float4 xv = reinterpret_cast<const float4*>(x)[i];
    float4 hv = reinterpret_cast<const float4*>(g_hp)[i];
    float4 sc = reinterpret_cast<const float4*>(g_scale)[c4];
    float4 sh = reinterpret_cast<const float4*>(g_shift)[c4];
    float4 o;
    o.x = xv.x + ALPHA_C * fmaf(hv.x, sc.x, sh.x);
    o.y = xv.y + ALPHA_C * fmaf(hv.y, sc.y, sh.y);
    o.z = xv.z + ALPHA_C * fmaf(hv.z, sc.z, sh.z);
    o.w = xv.w + ALPHA_C * fmaf(hv.w, sc.w, sh.w);
    reinterpret_cast<float4*>(out)[i] = o;
}

// ---------------- launch ----------------
extern "C" void kernel_launch(void* const* d_in, const int* in_sizes, int n_in,
                              void* d_out, int out_size) {
    const float* x    = (const float*)d_in[0];
    const float* adj  = (const float*)d_in[1];
    const float* W    = (const float*)d_in[2];
    const float* Wq   = (const float*)d_in[3];
    const float* bq   = (const float*)d_in[4];
    const float* Wk   = (const float*)d_in[5];
    const float* bk   = (const float*)d_in[6];
    const float* bn_g = (const float*)d_in[7];
    const float* bn_b = (const float*)d_in[8];
    float* out = (float*)d_out;

    cudaFuncSetAttribute(gemm_mma, cudaFuncAttributeMaxDynamicSharedMemorySize, SMEM_GEMM);

    // prep: split x; build combined weight [W; WqW; WkW] and split
    xsplit<<<(ROWS * CC / 4) / 256, 256>>>(x);
    wprep<<<256, 512>>>(W, Wq, Wk);
    wsplit<<<(NOUT * CC) / 256, 256>>>(W);
    // [h | q | k] = x @ CW^T   (mma.sync bf16x3 + ldmatrix)
    gemm_mma<<<dim3(6, 512), 256, SMEM_GEMM>>>(bq, bk);
    // attention + message passing -> hp (+ BN partial sums)
    attn_kernel<<<NB, 256>>>(adj);
    // BN reductions + epilogue
    bn_red1<<<256, 512>>>();
    bn_stats2<<<1, 512>>>(bn_g, bn_b);
    bn_finalize<<<(ROWS * CC / 4) / 256, 256>>>(x, out);
}

// round 17
// speedup vs baseline: 2.6364x; 1.6980x over previous
#include <cuda_runtime.h>
#include <cuda_bf16.h>
#include <cstdint>
#include <math.h>

// Problem constants
#define NB   4096
#define VV   16
#define CC   512
#define HH   128
#define ROWS (NB * VV)          // 65536
#define NOUT 768                // h(512) | q(128) | k(128)
#define GAMMA_C 1.0f
#define ALPHA_C 1.0f
#define EPS_L1 1e-12f
#define EPS_BN 1e-5f

// ---------------- scratch (device globals; no allocation) ----------------
__device__ float g_h [ROWS * CC];                       // 134 MB
__device__ float g_qk[ROWS * 2 * HH];                   // 67 MB per-n [q_t|k_t], c-major
__device__ float g_hp[ROWS * CC];                       // 134 MB
__device__ __align__(16) __nv_bfloat16 g_xhi[ROWS * CC];   // 67 MB
__device__ __align__(16) __nv_bfloat16 g_xlo[ROWS * CC];   // 67 MB
__device__ __align__(16) __nv_bfloat16 g_cwhi[NOUT * CC];
__device__ __align__(16) __nv_bfloat16 g_cwlo[NOUT * CC];
__device__ float g_bsum  [NB * CC];                     // per-batch partial sums
__device__ float g_bsumsq[NB * CC];
__device__ float g_psum  [256 * CC];
__device__ float g_psumsq[256 * CC];
__device__ float g_scale[CC];
__device__ float g_shift[CC];

// ---------------- prep: split x into bf16 hi/lo --------------------------
__global__ __launch_bounds__(256)
void xsplit(const float* __restrict__ x) {
    const long i = (long)blockIdx.x * 256 + threadIdx.x;      // float4 idx
    float4 v = reinterpret_cast<const float4*>(x)[i];
    __nv_bfloat16 hx = __float2bfloat16(v.x), hy = __float2bfloat16(v.y);
    __nv_bfloat16 hz = __float2bfloat16(v.z), hw = __float2bfloat16(v.w);
    __nv_bfloat162 h01; h01.x = hx; h01.y = hy;
    __nv_bfloat162 h23; h23.x = hz; h23.y = hw;
    __nv_bfloat162 l01, l23;
    l01.x = __float2bfloat16(v.x - __bfloat162float(hx));
    l01.y = __float2bfloat16(v.y - __bfloat162float(hy));
    l23.x = __float2bfloat16(v.z - __bfloat162float(hz));
    l23.y = __float2bfloat16(v.w - __bfloat162float(hw));
    reinterpret_cast<__nv_bfloat162*>(g_xhi)[2 * i]     = h01;
    reinterpret_cast<__nv_bfloat162*>(g_xhi)[2 * i + 1] = h23;
    reinterpret_cast<__nv_bfloat162*>(g_xlo)[2 * i]     = l01;
    reinterpret_cast<__nv_bfloat162*>(g_xlo)[2 * i + 1] = l23;
}

// ------- prep: combined weight [W; WqW; WkW] -> bf16 hi/lo (fused) -------
__global__ __launch_bounds__(512)
void wfused(const float* __restrict__ W, const float* __restrict__ Wq,
            const float* __restrict__ Wk) {
    const int o = blockIdx.x;            // 0..767
    const int c = threadIdx.x;           // 0..511
    float v;
    if (o < CC) {
        v = W[o * CC + c];
    } else {
        const int oo = o - CC;           // 0..255
        const float* Ws = (oo < 128) ? (Wq + oo * CC) : (Wk + (oo - 128) * CC);
        float acc = 0.f;
        for (int j = 0; j < CC; ++j)
            acc = fmaf(Ws[j], W[j * CC + c], acc);
        v = acc;
    }
    __nv_bfloat16 hi = __float2bfloat16(v);
    g_cwhi[o * CC + c] = hi;
    g_cwlo[o * CC + c] = __float2bfloat16(v - __bfloat162float(hi));
}

// ================= main GEMM: [h|q|k] = x @ CW^T ==========================
// mma.sync bf16x3 + ldmatrix fragments; cp.async double-buffered K=32 stages.

#define ROW_B 80                         // bytes per 32-bf16 row (64B data + 16B pad)
#define TILE_B (128 * ROW_B)             // 10240 per operand tile
#define STAGE_B (4 * TILE_B)             // Ahi|Alo|Bhi|Blo = 40960
#define SMEM_GEMM (2 * STAGE_B)          // 81920 double-buffered

__device__ __forceinline__ uint32_t smem_u32(const void* p) {
    uint32_t a;
    asm("{ .reg .u64 t; cvta.to.shared.u64 t, %1; cvt.u32.u64 %0, t; }" : "=r"(a) : "l"(p));
    return a;
}

#define CP16(dst, src) \
    asm volatile("cp.async.cg.shared.global [%0], [%1], 16;" :: "r"(dst), "l"(src))

#define MMA_BF16(d, a, b) \
    asm volatile("mma.sync.aligned.m16n8k16.row.col.f32.bf16.bf16.f32 " \
        "{%0,%1,%2,%3}, {%4,%5,%6,%7}, {%8,%9}, {%0,%1,%2,%3};" \
        : "+f"((d)[0]), "+f"((d)[1]), "+f"((d)[2]), "+f"((d)[3]) \
        : "r"((a)[0]), "r"((a)[1]), "r"((a)[2]), "r"((a)[3]), \
          "r"((b)[0]), "r"((b)[1]))

#define LDSM4(r0, r1, r2, r3, addr) \
    asm volatile("ldmatrix.sync.aligned.m8n8.x4.shared.b16 {%0,%1,%2,%3}, [%4];" \
        : "=r"(r0), "=r"(r1), "=r"(r2), "=r"(r3) : "r"(addr))

__global__ __launch_bounds__(256, 2)
void gemm_mma(const float* __restrict__ bq, const float* __restrict__ bk) {
    extern __shared__ char smem[];
    const int tid = threadIdx.x;
    const int wid = tid >> 5, lid = tid & 31;
    const int wm  = wid >> 2, wn = wid & 3;       // warp grid 2x4
    const int g   = lid >> 2, t  = lid & 3;
    const int tn  = blockIdx.x;                   // 0..5 (N tile of 128)
    const long bm = (long)blockIdx.y * 128;
    const long bn = (long)tn * 128;

    float acc[4][4][4];
#pragma unroll
    for (int i = 0; i < 4; ++i)
#pragma unroll
        for (int j = 0; j < 4; ++j)
#pragma unroll
            for (int r = 0; r < 4; ++r) acc[i][j][r] = 0.f;

    // ldmatrix per-lane sub-addresses
    const int rin    = lid & 7;
    const int arow_l = ((lid >> 3) & 1) * 8 + rin;   // row within 16-row A frag
    const int acolt  = (lid >> 4) * 16;              // 0 or 16 bytes (k half)
    const int brow_l = (lid >> 4) * 8 + rin;         // row within 16-row B pair
    const int bcolt  = ((lid >> 3) & 1) * 16;        // 0 or 16 bytes (k half)

    const uint32_t smem0 = smem_u32(smem);

    // --- stage loader: 2048 16B chunks, 8 per thread
    const int lrow = tid >> 2;        // 0..63
    const int lcc  = tid & 3;         // 16B chunk in row
#define LOAD_STAGE(sbuf, k0)                                                     \
    do {                                                                         \
        char* base_ = smem + (sbuf) * STAGE_B;                                   \
        _Pragma("unroll")                                                        \
        for (int u = 0; u < 8; ++u) {                                            \
            const int tile_ = u >> 1;                                            \
            const int row_  = lrow + (u & 1) * 64;                               \
            const __nv_bfloat16* gs_;                                            \
            if      (tile_ == 0) gs_ = g_xhi  + (bm + row_) * CC + (k0) + lcc * 8; \
            else if (tile_ == 1) gs_ = g_xlo  + (bm + row_) * CC + (k0) + lcc * 8; \
            else if (tile_ == 2) gs_ = g_cwhi + (bn + row_) * CC + (k0) + lcc * 8; \
            else                 gs_ = g_cwlo + (bn + row_) * CC + (k0) + lcc * 8; \
            uint32_t d_ = smem_u32(base_ + tile_ * TILE_B + row_ * ROW_B + lcc * 16); \
            CP16(d_, gs_);                                                       \
        }                                                                        \
        asm volatile("cp.async.commit_group;");                                  \
    } while (0)

    LOAD_STAGE(0, 0);

    for (int s = 0; s < 16; ++s) {
        if (s + 1 < 16) {
            LOAD_STAGE((s + 1) & 1, (s + 1) * 32);
            asm volatile("cp.async.wait_group 1;");
        } else {
            asm volatile("cp.async.wait_group 0;");
        }
        __syncthreads();

        const uint32_t base = smem0 + (s & 1) * STAGE_B;
        const uint32_t Ahi = base;
        const uint32_t Alo = base + TILE_B;
        const uint32_t Bhi = base + 2 * TILE_B;
        const uint32_t Blo = base + 3 * TILE_B;

#pragma unroll
        for (int kk = 0; kk < 2; ++kk) {
            const int acol = kk * 32 + acolt;
            const int bcol = kk * 32 + bcolt;
            uint32_t ah[4][4], al[4][4], bh[4][2], bl[4][2];
#pragma unroll
            for (int i = 0; i < 4; ++i) {
                const uint32_t aoff = (uint32_t)((wm * 64 + i * 16 + arow_l) * ROW_B + acol);
                LDSM4(ah[i][0], ah[i][1], ah[i][2], ah[i][3], Ahi + aoff);
                LDSM4(al[i][0], al[i][1], al[i][2], al[i][3], Alo + aoff);
            }
#pragma unroll
            for (int p = 0; p < 2; ++p) {
                const uint32_t boff = (uint32_t)((wn * 32 + p * 16 + brow_l) * ROW_B + bcol);
                LDSM4(bh[2*p][0], bh[2*p][1], bh[2*p+1][0], bh[2*p+1][1], Bhi + boff);
                LDSM4(bl[2*p][0], bl[2*p][1], bl[2*p+1][0], bl[2*p+1][1], Blo + boff);
            }
#pragma unroll
            for (int i = 0; i < 4; ++i)
#pragma unroll
                for (int j = 0; j < 4; ++j) {
                    MMA_BF16(acc[i][j], ah[i], bh[j]);
                    MMA_BF16(acc[i][j], ah[i], bl[j]);
                    MMA_BF16(acc[i][j], al[i], bh[j]);
                }
        }
        __syncthreads();   // compute done before next stage overwrites buffer
    }

    // --- epilogue: D rows g/g+8, cols t*2,t*2+1 per (i,j)
#pragma unroll
    for (int i = 0; i < 4; ++i) {
#pragma unroll
        for (int j = 0; j < 4; ++j) {
            const int coll = wn * 32 + j * 8 + t * 2;     // 0..127 within block
#pragma unroll
            for (int half = 0; half < 2; ++half) {
                const long grow = bm + wm * 64 + i * 16 + g + half * 8;
                float v0 = acc[i][j][half * 2 + 0];
                float v1 = acc[i][j][half * 2 + 1];
                if (tn < 4) {
                    float2 o; o.x = v0; o.y = v1;
                    *reinterpret_cast<float2*>(&g_h[grow * CC + tn * 128 + coll]) = o;
                } else {
                    const float* bias = (tn == 4) ? bq : bk;
                    // TRANSPOSED per-n store: q_t[c][v] (c-major) for conflict-free attn
                    float* dst = g_qk + (grow >> 4) * (2 * VV * HH)
                               + ((tn == 5) ? VV * HH : 0) + (grow & 15);
                    dst[(coll + 0) * VV] = v0 + bias[coll];
                    dst[(coll + 1) * VV] = v1 + bias[coll + 1];
                }
            }
        }
    }
}

// ---------------- per-n attention + message passing + BN partials --------
__global__ __launch_bounds__(256)
void attn_kernel(const float* __restrict__ adj) {
    const int n   = blockIdx.x;
    const int tid = threadIdx.x;

    __shared__ float buf[VV * CC];       // 32KB: first q_t|k_t, then h
    __shared__ float graph[VV][VV];

    // load q_t|k_t (4096 floats) vectorized
    {
        const float4* qkg = reinterpret_cast<const float4*>(g_qk + (long)n * 2 * VV * HH);
        float4* b4 = reinterpret_cast<float4*>(buf);
#pragma unroll
        for (int u = 0; u < 4; ++u) b4[tid + u * 256] = qkg[tid + u * 256];
    }
    __syncthreads();

    {   // all 256 threads: one (v,w) logit each; conflict-free smem (stride-16 transposed)
        const int v = tid >> 4, w = tid & 15;
        const float* qt = buf + v;              // q_t[c*16+v]
        const float* kt = buf + VV * HH + w;    // k_t[c*16+w]
        float s = 0.f;
#pragma unroll 16
        for (int c = 0; c < HH; ++c) s = fmaf(qt[c * VV], kt[c * VV], s);
        // softmax over w within each 16-lane group (deterministic shfl tree)
        float m = s;
#pragma unroll
        for (int o = 8; o; o >>= 1) m = fmaxf(m, __shfl_xor_sync(0xFFFFFFFFu, m, o, 16));
        float e = expf(s - m);
        float es = e;
#pragma unroll
        for (int o = 8; o; o >>= 1) es += __shfl_xor_sync(0xFFFFFFFFu, es, o, 16);
        float a = adj[(long)n * (VV * VV) + tid];
        float rs = fabsf(a);
#pragma unroll
        for (int o = 8; o; o >>= 1) rs += __shfl_xor_sync(0xFFFFFFFFu, rs, o, 16);
        rs = fmaxf(rs, EPS_L1);
        graph[v][w] = (a / rs + GAMMA_C * (e / es)) * (1.f / (1.f + GAMMA_C));
    }
    __syncthreads();

    // reload buf with h_n (vectorized), then hp = relu(graph @ h_n)
    {
        const float4* hg4 = reinterpret_cast<const float4*>(g_h + (long)n * VV * CC);
        float4* b4 = reinterpret_cast<float4*>(buf);
#pragma unroll
        for (int u = 0; u < 8; ++u) b4[tid + u * 256] = hg4[tid + u * 256];
    }
    __syncthreads();

    float* outb = g_hp + (long)n * VV * CC;
    for (int cc = tid; cc < CC; cc += 256) {
        float hv[VV];
#pragma unroll
        for (int w = 0; w < VV; ++w) hv[w] = buf[w * CC + cc];
        float ps = 0.f, pq = 0.f;
#pragma unroll
        for (int v = 0; v < VV; ++v) {
            float s = 0.f;
#pragma unroll
            for (int w = 0; w < VV; ++w) s = fmaf(graph[v][w], hv[w], s);
            s = fmaxf(s, 0.f);
            outb[v * CC + cc] = s;
            ps += s;
            pq = fmaf(s, s, pq);
        }
        g_bsum  [(long)n * CC + cc] = ps;     // fused BN pass-1 partials
        g_bsumsq[(long)n * CC + cc] = pq;
    }
}

// ---------------- BN reductions (deterministic tree) ---------------------
__global__ __launch_bounds__(512)
void bn_red1() {
    const int b = blockIdx.x;            // 256 blocks, 16 batches each
    const int c = threadIdx.x;           // channel
    float s = 0.f, q = 0.f;
#pragma unroll
    for (int i = 0; i < 16; ++i) {
        const long n = (long)b * 16 + i;
        s += g_bsum  [n * CC + c];
        q += g_bsumsq[n * CC + c];
    }
    g_psum  [b * CC + c] = s;
    g_psumsq[b * CC + c] = q;
}

__global__ __launch_bounds__(512)
void bn_stats2(const float* __restrict__ bn_g, const float* __restrict__ bn_b) {
    const int c = threadIdx.x;
    float s = 0.f, sq = 0.f;
    for (int i = 0; i < 256; ++i) {
        s  += g_psum  [i * CC + c];
        sq += g_psumsq[i * CC + c];
    }
    const float inv_n = 1.f / (float)ROWS;
    float mean = s * inv_n;
    float var  = sq * inv_n - mean * mean;
    float sc   = bn_g[c] * rsqrtf(var + EPS_BN);
    g_scale[c] = sc;
    g_shift[c] = bn_b[c] - mean * sc;
}

// ---------------- epilogue: out = x + alpha*(hp*scale + shift) -----------
__global__ __launch_bounds__(256)
void bn_finalize(const float* __restrict__ x, float* __restrict__ out) {
    const long i  = (long)blockIdx.x * 256 + threadIdx.x;
    const int  c4 = (int)(i & 127);
    float4 xv = reinterpret_cast<const float4*>(x)[i];
    float4 hv = reinterpret_cast<const float4*>(g_hp)[i];
    float4 sc = reinterpret_cast<const float4*>(g_scale)[c4];
    float4 sh = reinterpret_cast<const float4*>(g_shift)[c4];
    float4 o;
    o.x = xv.x + ALPHA_C * fmaf(hv.x, sc.x, sh.x);
    o.y = xv.y + ALPHA_C * fmaf(hv.y, sc.y, sh.y);
    o.z = xv.z + ALPHA_C * fmaf(hv.z, sc.z, sh.z);
    o.w = xv.w + ALPHA_C * fmaf(hv.w, sc.w, sh.w);
    reinterpret_cast<float4*>(out)[i] = o;
}

// ---------------- launch ----------------
extern "C" void kernel_launch(void* const* d_in, const int* in_sizes, int n_in,
                              void* d_out, int out_size) {
    const float* x    = (const float*)d_in[0];
    const float* adj  = (const float*)d_in[1];
    const float* W    = (const float*)d_in[2];
    const float* Wq   = (const float*)d_in[3];
    const float* bq   = (const float*)d_in[4];
    const float* Wk   = (const float*)d_in[5];
    const float* bk   = (const float*)d_in[6];
    const float* bn_g = (const float*)d_in[7];
    const float* bn_b = (const float*)d_in[8];
    float* out = (float*)d_out;

    cudaFuncSetAttribute(gemm_mma, cudaFuncAttributeMaxDynamicSharedMemorySize, SMEM_GEMM);

    // 1: split x; 2: combined weight [W; WqW; WkW] -> bf16 hi/lo
    xsplit<<<(ROWS * CC / 4) / 256, 256>>>(x);
    wfused<<<NOUT, 512>>>(W, Wq, Wk);
    // 3: [h | q_t | k_t] = x @ CW^T   (mma.sync bf16x3 + ldmatrix)
    gemm_mma<<<dim3(6, 512), 256, SMEM_GEMM>>>(bq, bk);
    // 4: attention + message passing -> hp (+ BN partials)  [ncu capture slot]
    attn_kernel<<<NB, 256>>>(adj);
    // BN reductions + epilogue
    bn_red1<<<256, 512>>>();
    bn_stats2<<<1, 512>>>(bn_g, bn_b);
    bn_finalize<<<(ROWS * CC / 4) / 256, 256>>>(x, out);
}